// round 7
// baseline (speedup 1.0000x reference)
#include <cuda_runtime.h>
#include <math.h>
#include <stdint.h>

namespace {
constexpr int B  = 4;
constexpr int L  = 2048;
constexpr int DM = 1024;
constexpr int H  = 16;
constexpr int DH = 64;
constexpr int U  = 38;          // int(5 * ln(2048))
constexpr int BH = B * H;       // 64
constexpr float SCALE = 0.125f; // 1/sqrt(64)
constexpr double LOGL = 7.624618986159398; // ln(2048)

constexpr int TQ = 128;    // queries per CTA
constexpr int TK = 128;    // keys per tile
constexpr int NT = L / TK; // 16 tiles
constexpr int AST = 68;    // padded smem row stride (floats): r*4+c bank pattern, 16B rows

constexpr int TILE_F  = TQ * AST;          // 8704 floats per matrix
constexpr int OFF_AHI = 0;
constexpr int OFF_ALO = TILE_F;
constexpr int OFF_BHI = 2 * TILE_F;
constexpr int OFF_BLO = 3 * TILE_F;
constexpr int OFF_RED = 4 * TILE_F;        // red[128][4][2]
constexpr int SMEM_BYTES = (4 * TILE_F + 128 * 4 * 2) * 4;  // 143,360 B

__device__ float g_kl[BH * L];
__device__ float g_sume[BH * L];
__device__ int   g_idx[BH * U];
} // namespace

// round-to-nearest tf32 (bit pattern in fp32 container, low 13 bits zero)
__device__ __forceinline__ float tf32r(float x) {
    uint32_t r;
    asm("cvt.rna.tf32.f32 %0, %1;" : "=r"(r) : "f"(x));
    return __uint_as_float(r);
}

#define MMA_TF32(d0, d1, d2, d3, a0, a1, a2, a3, b0, b1)                    \
    asm volatile(                                                           \
        "mma.sync.aligned.m16n8k8.row.col.f32.tf32.tf32.f32 "               \
        "{%0,%1,%2,%3}, {%4,%5,%6,%7}, {%8,%9}, {%0,%1,%2,%3};"             \
        : "+f"(d0), "+f"(d1), "+f"(d2), "+f"(d3)                            \
        : "r"(a0), "r"(a1), "r"(a2), "r"(a3), "r"(b0), "r"(b1))

// Accurate exp(x): 2^(x*log2e), range-reduced, degree-7 poly. ~1 ulp.
__device__ __forceinline__ float exp_acc(float x) {
    float t = x * 1.4426950408889634f;
    float n = rintf(t);
    float f = t - n;
    float p = 1.5252733804059840e-05f;
    p = fmaf(p, f, 1.5403530393381609e-04f);
    p = fmaf(p, f, 1.3333558146428443e-03f);
    p = fmaf(p, f, 9.6181291076284772e-03f);
    p = fmaf(p, f, 5.5504108664821580e-02f);
    p = fmaf(p, f, 2.4022650695910071e-01f);
    p = fmaf(p, f, 6.9314718055994531e-01f);
    p = fmaf(p, f, 1.0f);
    return p * __int_as_float(((int)n + 127) << 23);
}

// Kahan compensated add (no muls -> safe under fma contraction)
__device__ __forceinline__ void kadd(float& s, float& comp, float v) {
    float y = v - comp;
    float t = s + y;
    comp = (t - s) - y;
    s = t;
}

__device__ __forceinline__ void split4(float* hi, float* lo, int row, int col,
                                       float4 v) {
    float hx = tf32r(v.x), hy = tf32r(v.y), hz = tf32r(v.z), hw = tf32r(v.w);
    float lx = tf32r(v.x - hx), ly = tf32r(v.y - hy);
    float lz = tf32r(v.z - hz), lw = tf32r(v.w - hw);
    *reinterpret_cast<float4*>(hi + row * AST + col) = make_float4(hx, hy, hz, hw);
    *reinterpret_cast<float4*>(lo + row * AST + col) = make_float4(lx, ly, lz, lw);
}

// ---------------------------------------------------------------------------
// Pass 1: per-query streaming KL via tf32x3 mma.sync.
// CTA = 256 thr (8 warps, 2 row-groups x 4 col-groups), 128 q x 2048 k.
// ---------------------------------------------------------------------------
__global__ void __launch_bounds__(256, 1) kl_mma(const float* __restrict__ Q,
                                                 const float* __restrict__ Km) {
    extern __shared__ float sm[];
    float* Ah = sm + OFF_AHI;
    float* Al = sm + OFF_ALO;
    float* Bh = sm + OFF_BHI;
    float* Bl = sm + OFF_BLO;
    float* red = sm + OFF_RED;

    const int tid = threadIdx.x;
    const int lane = tid & 31, wid = tid >> 5;
    const int wm = wid >> 2, wn = wid & 3;   // warp grid 2 x 4
    const int g = lane >> 2, c = lane & 3;   // fragment lane coords
    const int bh = blockIdx.x, b = bh >> 4, h = bh & 15;
    const int q0 = blockIdx.y * TQ;

    const float* Qb = Q + ((size_t)b * L + q0) * DM + h * DH;
    const float* Kb = Km + (size_t)b * L * DM + h * DH;

    // load + split Q tile [128 x 64]
#pragma unroll
    for (int it = 0; it < 8; ++it) {
        int idx = it * 256 + tid;
        int row = idx >> 4, c4 = (idx & 15) * 4;
        float4 v = *reinterpret_cast<const float4*>(Qb + (size_t)row * DM + c4);
        split4(Ah, Al, row, c4, v);
    }
    // load + split K tile 0 [128 keys x 64 dims]
#pragma unroll
    for (int it = 0; it < 8; ++it) {
        int idx = it * 256 + tid;
        int row = idx >> 4, c4 = (idx & 15) * 4;
        float4 v = *reinterpret_cast<const float4*>(Kb + (size_t)row * DM + c4);
        split4(Bh, Bl, row, c4, v);
    }
    __syncthreads();

    float te[8], tse[8], tec[8], tsec[8];
#pragma unroll
    for (int i = 0; i < 8; ++i) { te[i] = tse[i] = tec[i] = tsec[i] = 0.f; }

    for (int t = 0; t < NT; ++t) {
        // prefetch next K tile into registers (latency hides behind mma phase)
        float4 pf[8];
        if (t + 1 < NT) {
            const float* Kt = Kb + (size_t)(t + 1) * TK * DM;
#pragma unroll
            for (int it = 0; it < 8; ++it) {
                int idx = it * 256 + tid;
                int row = idx >> 4, c4 = (idx & 15) * 4;
                pf[it] = *reinterpret_cast<const float4*>(Kt + (size_t)row * DM + c4);
            }
        }

        float acc[4][4][4];
#pragma unroll
        for (int mt = 0; mt < 4; ++mt)
#pragma unroll
            for (int nt = 0; nt < 4; ++nt)
#pragma unroll
                for (int r = 0; r < 4; ++r) acc[mt][nt][r] = 0.f;

        // --- 3-split tf32 MMA over this K tile ---
#pragma unroll
        for (int sp = 0; sp < 3; ++sp) {
            const float* As = (sp == 2) ? Al : Ah;
            const float* Bs = (sp == 1) ? Bl : Bh;
#pragma unroll
            for (int ks = 0; ks < 8; ++ks) {
                uint32_t a[4][4];
#pragma unroll
                for (int mt = 0; mt < 4; ++mt) {
                    const float* p = As + (wm * 64 + mt * 16 + g) * AST + ks * 8 + c;
                    a[mt][0] = __float_as_uint(p[0]);
                    a[mt][1] = __float_as_uint(p[8 * AST]);
                    a[mt][2] = __float_as_uint(p[4]);
                    a[mt][3] = __float_as_uint(p[8 * AST + 4]);
                }
#pragma unroll
                for (int nt = 0; nt < 4; ++nt) {
                    const float* p = Bs + (wn * 32 + nt * 8 + g) * AST + ks * 8 + c;
                    uint32_t b0 = __float_as_uint(p[0]);
                    uint32_t b1 = __float_as_uint(p[4]);
#pragma unroll
                    for (int mt = 0; mt < 4; ++mt)
                        MMA_TF32(acc[mt][nt][0], acc[mt][nt][1],
                                 acc[mt][nt][2], acc[mt][nt][3],
                                 a[mt][0], a[mt][1], a[mt][2], a[mt][3], b0, b1);
                }
            }
        }

        // --- epilogue: exp + accumulate (fp32 tile partials -> Kahan merge) ---
        float tte[8], ttse[8];
#pragma unroll
        for (int i = 0; i < 8; ++i) { tte[i] = ttse[i] = 0.f; }
#pragma unroll
        for (int mt = 0; mt < 4; ++mt)
#pragma unroll
            for (int nt = 0; nt < 4; ++nt)
#pragma unroll
                for (int r = 0; r < 4; ++r) {
                    float s = acc[mt][nt][r] * SCALE;
                    float e = exp_acc(s);
                    int slot = mt * 2 + (r >> 1);
                    tte[slot] += e;
                    ttse[slot] = fmaf(s, e, ttse[slot]);
                }
#pragma unroll
        for (int i = 0; i < 8; ++i) {
            kadd(te[i], tec[i], tte[i]);
            kadd(tse[i], tsec[i], ttse[i]);
        }

        __syncthreads();
        if (t + 1 < NT) {
#pragma unroll
            for (int it = 0; it < 8; ++it) {
                int idx = it * 256 + tid;
                int row = idx >> 4, c4 = (idx & 15) * 4;
                split4(Bh, Bl, row, c4, pf[it]);
            }
            __syncthreads();
        }
    }

    // fold compensation, reduce across the 4 lanes of each quad (c = 0..3)
#pragma unroll
    for (int i = 0; i < 8; ++i) {
        float s1 = te[i] + tec[i];
        float s2 = tse[i] + tsec[i];
        s1 += __shfl_xor_sync(0xFFFFFFFFu, s1, 1);
        s1 += __shfl_xor_sync(0xFFFFFFFFu, s1, 2);
        s2 += __shfl_xor_sync(0xFFFFFFFFu, s2, 1);
        s2 += __shfl_xor_sync(0xFFFFFFFFu, s2, 2);
        te[i] = s1;
        tse[i] = s2;
    }
    if (c == 0) {
#pragma unroll
        for (int slot = 0; slot < 8; ++slot) {
            int row = wm * 64 + (slot >> 1) * 16 + g + (slot & 1) * 8;
            red[row * 8 + wn * 2 + 0] = te[slot];
            red[row * 8 + wn * 2 + 1] = tse[slot];
        }
    }
    __syncthreads();

    if (tid < TQ) {
        int row = tid;
        float se = red[row * 8 + 0] + red[row * 8 + 2] +
                   red[row * 8 + 4] + red[row * 8 + 6];
        float ss = red[row * 8 + 1] + red[row * 8 + 3] +
                   red[row * 8 + 5] + red[row * 8 + 7];
        const int gi = bh * L + q0 + row;
        g_sume[gi] = se;
        g_kl[gi] = (float)((double)ss / (double)se - log((double)se) + LOGL);
    }
}

// ---------------------------------------------------------------------------
// Pass 2: iterative top-U argmax per (b,h). Ties -> lowest index (JAX top_k).
// ---------------------------------------------------------------------------
__global__ void __launch_bounds__(256) topk_pass() {
    const int bh  = blockIdx.x;
    const int tid = threadIdx.x;

    __shared__ float sv[L];
    __shared__ float rv[256];
    __shared__ int   ri[256];

    for (int i = tid; i < L; i += 256) sv[i] = g_kl[bh * L + i];
    __syncthreads();

    for (int u = 0; u < U; ++u) {
        float best = -INFINITY;
        int   bi   = L;
        for (int i = tid; i < L; i += 256) {
            float v = sv[i];
            if (v > best) { best = v; bi = i; }
        }
        rv[tid] = best;
        ri[tid] = bi;
        __syncthreads();
        for (int s = 128; s > 0; s >>= 1) {
            if (tid < s) {
                float v2 = rv[tid + s];
                int   i2 = ri[tid + s];
                if (v2 > rv[tid] || (v2 == rv[tid] && i2 < ri[tid])) {
                    rv[tid] = v2; ri[tid] = i2;
                }
            }
            __syncthreads();
        }
        if (tid == 0) {
            g_idx[bh * U + u] = ri[0];
            sv[ri[0]] = -INFINITY;
        }
        __syncthreads();
    }
}

// ---------------------------------------------------------------------------
// Pass 3: sparse attention for the U selected queries of each (b,h).
// Reuses pass-1 softmax denominators (sum of exp over full K, unshifted).
// ---------------------------------------------------------------------------
constexpr int KT3 = 64;

__global__ void __launch_bounds__(256) sparse_attn(const float* __restrict__ Q,
                                                   const float* __restrict__ Km,
                                                   const float* __restrict__ Vm,
                                                   float* __restrict__ out,
                                                   float* __restrict__ aw,
                                                   int write_aw) {
    const int bh  = blockIdx.x;
    const int b   = bh >> 4;
    const int h   = bh & 15;
    const int tid = threadIdx.x;

    __shared__ float qs[U][DH];
    __shared__ float se[U];
    __shared__ int   qidx[U];
    __shared__ float tile[KT3][DH + 1];
    __shared__ float w[U][KT3];

    if (tid < U) {
        int qi = g_idx[bh * U + tid];
        qidx[tid] = qi;
        se[tid]   = g_sume[bh * L + qi];
    }
    __syncthreads();
    for (int i = tid; i < U * DH; i += 256) {
        int u = i / DH, d = i % DH;
        qs[u][d] = Q[((size_t)b * L + qidx[u]) * DM + h * DH + d];
    }

    float acc[10];
#pragma unroll
    for (int j = 0; j < 10; ++j) acc[j] = 0.f;

    const float* Kb = Km + (size_t)b * L * DM + h * DH;
    const float* Vb = Vm + (size_t)b * L * DM + h * DH;

    for (int k0 = 0; k0 < L; k0 += KT3) {
        __syncthreads();
        for (int i = tid; i < KT3 * 16; i += 256) {
            int kk = i >> 4, d4 = i & 15;
            float4 v = reinterpret_cast<const float4*>(Kb + (size_t)(k0 + kk) * DM)[d4];
            tile[kk][d4 * 4 + 0] = v.x; tile[kk][d4 * 4 + 1] = v.y;
            tile[kk][d4 * 4 + 2] = v.z; tile[kk][d4 * 4 + 3] = v.w;
        }
        __syncthreads();
        for (int i = tid; i < U * KT3; i += 256) {
            int u = i / KT3, kk = i % KT3;
            float s = 0.f;
#pragma unroll
            for (int d = 0; d < DH; ++d) s = fmaf(qs[u][d], tile[kk][d], s);
            s *= SCALE;
            float ww = exp_acc(s) / se[u];
            w[u][kk] = ww;
            if (write_aw) aw[((size_t)bh * U + u) * L + k0 + kk] = ww;
        }
        __syncthreads();
        for (int i = tid; i < KT3 * 16; i += 256) {
            int kk = i >> 4, d4 = i & 15;
            float4 v = reinterpret_cast<const float4*>(Vb + (size_t)(k0 + kk) * DM)[d4];
            tile[kk][d4 * 4 + 0] = v.x; tile[kk][d4 * 4 + 1] = v.y;
            tile[kk][d4 * 4 + 2] = v.z; tile[kk][d4 * 4 + 3] = v.w;
        }
        __syncthreads();
#pragma unroll
        for (int j = 0; j < 10; ++j) {
            int item = tid + j * 256;
            if (item < U * DH) {
                int u = item / DH, d = item % DH;
                float a = acc[j];
#pragma unroll
                for (int kk = 0; kk < KT3; ++kk) a = fmaf(w[u][kk], tile[kk][d], a);
                acc[j] = a;
            }
        }
    }
    __syncthreads();

#pragma unroll
    for (int j = 0; j < 10; ++j) {
        int item = tid + j * 256;
        if (item < U * DH) {
            int u = item / DH, d = item % DH;
            out[((size_t)b * L + qidx[u]) * DM + h * DH + d] = acc[j];
        }
    }
}

// ---------------------------------------------------------------------------
extern "C" void kernel_launch(void* const* d_in, const int* in_sizes, int n_in,
                              void* d_out, int out_size) {
    const float* Q = (const float*)d_in[0];
    const float* K = (const float*)d_in[1];
    const float* V = (const float*)d_in[2];
    float* out = (float*)d_out;

    const size_t out_elems = (size_t)B * L * DM;
    const size_t aw_elems  = (size_t)BH * U * L;
    const int write_aw = ((size_t)out_size >= out_elems + aw_elems) ? 1 : 0;
    float* aw = out + out_elems;

    cudaFuncSetAttribute(kl_mma, cudaFuncAttributeMaxDynamicSharedMemorySize,
                         SMEM_BYTES);

    cudaMemsetAsync(d_out, 0, out_elems * sizeof(float), 0);

    kl_mma<<<dim3(BH, L / TQ), 256, SMEM_BYTES>>>(Q, K);
    topk_pass<<<BH, 256>>>();
    sparse_attn<<<BH, 256>>>(Q, K, V, out, aw, write_aw);
}

// round 9
// speedup vs baseline: 1.3630x; 1.3630x over previous
#include <cuda_runtime.h>
#include <math.h>
#include <stdint.h>

namespace {
constexpr int B  = 4;
constexpr int L  = 2048;
constexpr int DM = 1024;
constexpr int H  = 16;
constexpr int DH = 64;
constexpr int U  = 38;          // int(5 * ln(2048))
constexpr int BH = B * H;       // 64
constexpr float SCALE = 0.125f; // 1/sqrt(64)
constexpr double LOGL = 7.624618986159398; // ln(2048)

constexpr int TQ = 128;    // queries per CTA
constexpr int TK = 128;    // keys per tile
constexpr int NT = L / TK; // 16 tiles
constexpr int AST = 68;    // padded smem row stride (floats)

constexpr int TILE_F  = TQ * AST;          // 8704 floats per matrix
constexpr int OFF_AHI = 0;
constexpr int OFF_ALO = TILE_F;
constexpr int OFF_BHI = 2 * TILE_F;
constexpr int OFF_BLO = 3 * TILE_F;
constexpr int OFF_RED = 4 * TILE_F;        // red[128][4][2]
constexpr int SMEM_BYTES = (4 * TILE_F + 128 * 4 * 2) * 4;  // 143,360 B

__device__ float g_kl[BH * L];
__device__ float g_sume[BH * L];
__device__ int   g_idx[BH * U];
} // namespace

// round-to-nearest tf32 (bit pattern in fp32 container, low 13 bits zero)
__device__ __forceinline__ float tf32r(float x) {
    uint32_t r;
    asm("cvt.rna.tf32.f32 %0, %1;" : "=r"(r) : "f"(x));
    return __uint_as_float(r);
}

#define MMA_TF32(d0, d1, d2, d3, a0, a1, a2, a3, b0, b1)                    \
    asm volatile(                                                           \
        "mma.sync.aligned.m16n8k8.row.col.f32.tf32.tf32.f32 "               \
        "{%0,%1,%2,%3}, {%4,%5,%6,%7}, {%8,%9}, {%0,%1,%2,%3};"             \
        : "+f"(d0), "+f"(d1), "+f"(d2), "+f"(d3)                            \
        : "r"(a0), "r"(a1), "r"(a2), "r"(a3), "r"(b0), "r"(b1))

// Accurate exp(x): 2^(x*log2e), range-reduced, degree-7 poly. ~1 ulp.
__device__ __forceinline__ float exp_acc(float x) {
    float t = x * 1.4426950408889634f;
    float n = rintf(t);
    float f = t - n;
    float p = 1.5252733804059840e-05f;
    p = fmaf(p, f, 1.5403530393381609e-04f);
    p = fmaf(p, f, 1.3333558146428443e-03f);
    p = fmaf(p, f, 9.6181291076284772e-03f);
    p = fmaf(p, f, 5.5504108664821580e-02f);
    p = fmaf(p, f, 2.4022650695910071e-01f);
    p = fmaf(p, f, 6.9314718055994531e-01f);
    p = fmaf(p, f, 1.0f);
    return p * __int_as_float(((int)n + 127) << 23);
}

// Kahan compensated add (no muls -> safe under fma contraction)
__device__ __forceinline__ void kadd(float& s, float& comp, float v) {
    float y = v - comp;
    float t = s + y;
    comp = (t - s) - y;
    s = t;
}

__device__ __forceinline__ void split4(float* hi, float* lo, int row, int col,
                                       float4 v) {
    float hx = tf32r(v.x), hy = tf32r(v.y), hz = tf32r(v.z), hw = tf32r(v.w);
    float lx = tf32r(v.x - hx), ly = tf32r(v.y - hy);
    float lz = tf32r(v.z - hz), lw = tf32r(v.w - hw);
    *reinterpret_cast<float4*>(hi + row * AST + col) = make_float4(hx, hy, hz, hw);
    *reinterpret_cast<float4*>(lo + row * AST + col) = make_float4(lx, ly, lz, lw);
}

// ---------------------------------------------------------------------------
// Pass 1: per-query streaming KL via tf32x3 mma.sync.
// CTA = 512 thr (16 warps, 4 row-groups x 4 col-groups), 128 q x 2048 k.
// Each warp: 32 q-rows x 32 k-cols -> acc[2][4][4] (32 regs, no spills).
// ---------------------------------------------------------------------------
__global__ void __launch_bounds__(512, 1) kl_mma(const float* __restrict__ Q,
                                                 const float* __restrict__ Km) {
    extern __shared__ float sm[];
    float* Ah = sm + OFF_AHI;
    float* Al = sm + OFF_ALO;
    float* Bh = sm + OFF_BHI;
    float* Bl = sm + OFF_BLO;
    float* red = sm + OFF_RED;

    const int tid = threadIdx.x;
    const int lane = tid & 31, wid = tid >> 5;
    const int wm = wid >> 2, wn = wid & 3;   // warp grid 4 x 4
    const int g = lane >> 2, c = lane & 3;   // fragment lane coords
    const int bh = blockIdx.x, b = bh >> 4, h = bh & 15;
    const int q0 = blockIdx.y * TQ;

    const float* Qb = Q + ((size_t)b * L + q0) * DM + h * DH;
    const float* Kb = Km + (size_t)b * L * DM + h * DH;

    // load + split Q tile [128 x 64]
#pragma unroll
    for (int it = 0; it < 4; ++it) {
        int idx = it * 512 + tid;
        int row = idx >> 4, c4 = (idx & 15) * 4;
        float4 v = *reinterpret_cast<const float4*>(Qb + (size_t)row * DM + c4);
        split4(Ah, Al, row, c4, v);
    }
    // load + split K tile 0 [128 keys x 64 dims]
#pragma unroll
    for (int it = 0; it < 4; ++it) {
        int idx = it * 512 + tid;
        int row = idx >> 4, c4 = (idx & 15) * 4;
        float4 v = *reinterpret_cast<const float4*>(Kb + (size_t)row * DM + c4);
        split4(Bh, Bl, row, c4, v);
    }
    __syncthreads();

    float te[4], tse[4], tec[4], tsec[4];
#pragma unroll
    for (int i = 0; i < 4; ++i) { te[i] = tse[i] = tec[i] = tsec[i] = 0.f; }

    for (int t = 0; t < NT; ++t) {
        // prefetch next K tile into registers (latency hides behind mma phase)
        float4 pf[4];
        if (t + 1 < NT) {
            const float* Kt = Kb + (size_t)(t + 1) * TK * DM;
#pragma unroll
            for (int it = 0; it < 4; ++it) {
                int idx = it * 512 + tid;
                int row = idx >> 4, c4 = (idx & 15) * 4;
                pf[it] = *reinterpret_cast<const float4*>(Kt + (size_t)row * DM + c4);
            }
        }

        float acc[2][4][4];
#pragma unroll
        for (int mt = 0; mt < 2; ++mt)
#pragma unroll
            for (int nt = 0; nt < 4; ++nt)
#pragma unroll
                for (int r = 0; r < 4; ++r) acc[mt][nt][r] = 0.f;

        // --- 3-split tf32 MMA over this K tile ---
#pragma unroll
        for (int sp = 0; sp < 3; ++sp) {
            const float* As = (sp == 2) ? Al : Ah;
            const float* Bs = (sp == 1) ? Bl : Bh;
#pragma unroll
            for (int ks = 0; ks < 8; ++ks) {
                uint32_t a[2][4];
#pragma unroll
                for (int mt = 0; mt < 2; ++mt) {
                    const float* p = As + (wm * 32 + mt * 16 + g) * AST + ks * 8 + c;
                    a[mt][0] = __float_as_uint(p[0]);
                    a[mt][1] = __float_as_uint(p[8 * AST]);
                    a[mt][2] = __float_as_uint(p[4]);
                    a[mt][3] = __float_as_uint(p[8 * AST + 4]);
                }
#pragma unroll
                for (int nt = 0; nt < 4; ++nt) {
                    const float* p = Bs + (wn * 32 + nt * 8 + g) * AST + ks * 8 + c;
                    uint32_t b0 = __float_as_uint(p[0]);
                    uint32_t b1 = __float_as_uint(p[4]);
#pragma unroll
                    for (int mt = 0; mt < 2; ++mt)
                        MMA_TF32(acc[mt][nt][0], acc[mt][nt][1],
                                 acc[mt][nt][2], acc[mt][nt][3],
                                 a[mt][0], a[mt][1], a[mt][2], a[mt][3], b0, b1);
                }
            }
        }

        // --- epilogue: exp + accumulate (fp32 tile partials -> Kahan merge) ---
        float tte[4], ttse[4];
#pragma unroll
        for (int i = 0; i < 4; ++i) { tte[i] = ttse[i] = 0.f; }
#pragma unroll
        for (int mt = 0; mt < 2; ++mt)
#pragma unroll
            for (int nt = 0; nt < 4; ++nt)
#pragma unroll
                for (int r = 0; r < 4; ++r) {
                    float s = acc[mt][nt][r] * SCALE;
                    float e = exp_acc(s);
                    int slot = mt * 2 + (r >> 1);
                    tte[slot] += e;
                    ttse[slot] = fmaf(s, e, ttse[slot]);
                }
#pragma unroll
        for (int i = 0; i < 4; ++i) {
            kadd(te[i], tec[i], tte[i]);
            kadd(tse[i], tsec[i], ttse[i]);
        }

        __syncthreads();
        if (t + 1 < NT) {
#pragma unroll
            for (int it = 0; it < 4; ++it) {
                int idx = it * 512 + tid;
                int row = idx >> 4, c4 = (idx & 15) * 4;
                split4(Bh, Bl, row, c4, pf[it]);
            }
            __syncthreads();
        }
    }

    // fold compensation, reduce across the 4 lanes of each quad (c = 0..3)
#pragma unroll
    for (int i = 0; i < 4; ++i) {
        float s1 = te[i] + tec[i];
        float s2 = tse[i] + tsec[i];
        s1 += __shfl_xor_sync(0xFFFFFFFFu, s1, 1);
        s1 += __shfl_xor_sync(0xFFFFFFFFu, s1, 2);
        s2 += __shfl_xor_sync(0xFFFFFFFFu, s2, 1);
        s2 += __shfl_xor_sync(0xFFFFFFFFu, s2, 2);
        te[i] = s1;
        tse[i] = s2;
    }
    if (c == 0) {
#pragma unroll
        for (int slot = 0; slot < 4; ++slot) {
            int row = wm * 32 + (slot >> 1) * 16 + g + (slot & 1) * 8;
            red[row * 8 + wn * 2 + 0] = te[slot];
            red[row * 8 + wn * 2 + 1] = tse[slot];
        }
    }
    __syncthreads();

    if (tid < TQ) {
        int row = tid;
        float se = red[row * 8 + 0] + red[row * 8 + 2] +
                   red[row * 8 + 4] + red[row * 8 + 6];
        float ss = red[row * 8 + 1] + red[row * 8 + 3] +
                   red[row * 8 + 5] + red[row * 8 + 7];
        const int gi = bh * L + q0 + row;
        g_sume[gi] = se;
        g_kl[gi] = (float)((double)ss / (double)se - log((double)se) + LOGL);
    }
}

// ---------------------------------------------------------------------------
// Pass 2: iterative top-U argmax per (b,h). Ties -> lowest index (JAX top_k).
// ---------------------------------------------------------------------------
__global__ void __launch_bounds__(256) topk_pass() {
    const int bh  = blockIdx.x;
    const int tid = threadIdx.x;

    __shared__ float sv[L];
    __shared__ float rv[256];
    __shared__ int   ri[256];

    for (int i = tid; i < L; i += 256) sv[i] = g_kl[bh * L + i];
    __syncthreads();

    for (int u = 0; u < U; ++u) {
        float best = -INFINITY;
        int   bi   = L;
        for (int i = tid; i < L; i += 256) {
            float v = sv[i];
            if (v > best) { best = v; bi = i; }
        }
        rv[tid] = best;
        ri[tid] = bi;
        __syncthreads();
        for (int s = 128; s > 0; s >>= 1) {
            if (tid < s) {
                float v2 = rv[tid + s];
                int   i2 = ri[tid + s];
                if (v2 > rv[tid] || (v2 == rv[tid] && i2 < ri[tid])) {
                    rv[tid] = v2; ri[tid] = i2;
                }
            }
            __syncthreads();
        }
        if (tid == 0) {
            g_idx[bh * U + u] = ri[0];
            sv[ri[0]] = -INFINITY;
        }
        __syncthreads();
    }
}

// ---------------------------------------------------------------------------
// Pass 3: sparse attention for the U selected queries of each (b,h).
// Reuses pass-1 softmax denominators (sum of exp over full K, unshifted).
// ---------------------------------------------------------------------------
constexpr int KT3 = 64;

__global__ void __launch_bounds__(256) sparse_attn(const float* __restrict__ Q,
                                                   const float* __restrict__ Km,
                                                   const float* __restrict__ Vm,
                                                   float* __restrict__ out,
                                                   float* __restrict__ aw,
                                                   int write_aw) {
    const int bh  = blockIdx.x;
    const int b   = bh >> 4;
    const int h   = bh & 15;
    const int tid = threadIdx.x;

    __shared__ float qs[U][DH];
    __shared__ float se[U];
    __shared__ int   qidx[U];
    __shared__ float tile[KT3][DH + 1];
    __shared__ float w[U][KT3];

    if (tid < U) {
        int qi = g_idx[bh * U + tid];
        qidx[tid] = qi;
        se[tid]   = g_sume[bh * L + qi];
    }
    __syncthreads();
    for (int i = tid; i < U * DH; i += 256) {
        int u = i / DH, d = i % DH;
        qs[u][d] = Q[((size_t)b * L + qidx[u]) * DM + h * DH + d];
    }

    float acc[10];
#pragma unroll
    for (int j = 0; j < 10; ++j) acc[j] = 0.f;

    const float* Kb = Km + (size_t)b * L * DM + h * DH;
    const float* Vb = Vm + (size_t)b * L * DM + h * DH;

    for (int k0 = 0; k0 < L; k0 += KT3) {
        __syncthreads();
        for (int i = tid; i < KT3 * 16; i += 256) {
            int kk = i >> 4, d4 = i & 15;
            float4 v = reinterpret_cast<const float4*>(Kb + (size_t)(k0 + kk) * DM)[d4];
            tile[kk][d4 * 4 + 0] = v.x; tile[kk][d4 * 4 + 1] = v.y;
            tile[kk][d4 * 4 + 2] = v.z; tile[kk][d4 * 4 + 3] = v.w;
        }
        __syncthreads();
        for (int i = tid; i < U * KT3; i += 256) {
            int u = i / KT3, kk = i % KT3;
            float s = 0.f;
#pragma unroll
            for (int d = 0; d < DH; ++d) s = fmaf(qs[u][d], tile[kk][d], s);
            s *= SCALE;
            float ww = exp_acc(s) / se[u];
            w[u][kk] = ww;
            if (write_aw) aw[((size_t)bh * U + u) * L + k0 + kk] = ww;
        }
        __syncthreads();
        for (int i = tid; i < KT3 * 16; i += 256) {
            int kk = i >> 4, d4 = i & 15;
            float4 v = reinterpret_cast<const float4*>(Vb + (size_t)(k0 + kk) * DM)[d4];
            tile[kk][d4 * 4 + 0] = v.x; tile[kk][d4 * 4 + 1] = v.y;
            tile[kk][d4 * 4 + 2] = v.z; tile[kk][d4 * 4 + 3] = v.w;
        }
        __syncthreads();
#pragma unroll
        for (int j = 0; j < 10; ++j) {
            int item = tid + j * 256;
            if (item < U * DH) {
                int u = item / DH, d = item % DH;
                float a = acc[j];
#pragma unroll
                for (int kk = 0; kk < KT3; ++kk) a = fmaf(w[u][kk], tile[kk][d], a);
                acc[j] = a;
            }
        }
    }
    __syncthreads();

#pragma unroll
    for (int j = 0; j < 10; ++j) {
        int item = tid + j * 256;
        if (item < U * DH) {
            int u = item / DH, d = item % DH;
            out[((size_t)b * L + qidx[u]) * DM + h * DH + d] = acc[j];
        }
    }
}

// ---------------------------------------------------------------------------
extern "C" void kernel_launch(void* const* d_in, const int* in_sizes, int n_in,
                              void* d_out, int out_size) {
    const float* Q = (const float*)d_in[0];
    const float* K = (const float*)d_in[1];
    const float* V = (const float*)d_in[2];
    float* out = (float*)d_out;

    const size_t out_elems = (size_t)B * L * DM;
    const size_t aw_elems  = (size_t)BH * U * L;
    const int write_aw = ((size_t)out_size >= out_elems + aw_elems) ? 1 : 0;
    float* aw = out + out_elems;

    cudaFuncSetAttribute(kl_mma, cudaFuncAttributeMaxDynamicSharedMemorySize,
                         SMEM_BYTES);

    cudaMemsetAsync(d_out, 0, out_elems * sizeof(float), 0);

    kl_mma<<<dim3(BH, L / TQ), 512, SMEM_BYTES>>>(Q, K);
    topk_pass<<<BH, 256>>>();
    sparse_attn<<<BH, 256>>>(Q, K, V, out, aw, write_aw);
}

// round 10
// speedup vs baseline: 1.4847x; 1.0893x over previous
#include <cuda_runtime.h>
#include <math.h>
#include <stdint.h>

namespace {
constexpr int B  = 4;
constexpr int L  = 2048;
constexpr int DM = 1024;
constexpr int H  = 16;
constexpr int DH = 64;
constexpr int U  = 38;          // int(5 * ln(2048))
constexpr int BH = B * H;       // 64
constexpr float SCALE = 0.125f; // 1/sqrt(64)
constexpr float LOG2E = 1.4426950408889634f;
constexpr double LOGL = 7.624618986159398; // ln(2048)

constexpr int TQ = 128;    // queries per CTA
constexpr int TK = 128;    // keys per tile
constexpr int NT = L / TK; // 16 tiles

// fragment-major smem: A frag[rowblk(8)][ks(8)][lane(32)] float4 (slots a0..a3)
//                      B frag[keyblk(16)][ks(8)][lane(32)] float2 (slots b0,b1)
constexpr int FRAG_F  = 8192;              // floats per matrix-split (both A and B)
constexpr int OFF_AHI = 0;
constexpr int OFF_ALO = FRAG_F;
constexpr int OFF_BHI = 2 * FRAG_F;
constexpr int OFF_BLO = 3 * FRAG_F;
constexpr int OFF_RED = 4 * FRAG_F;        // red[128][4][2]
constexpr int SMEM_BYTES = (4 * FRAG_F + 128 * 8) * 4;  // 135,168 B

__device__ float g_kl[BH * L];
__device__ float g_sume[BH * L];
__device__ int   g_idx[BH * U];
} // namespace

// round-to-nearest tf32 (bit pattern in fp32 container, low 13 bits zero)
__device__ __forceinline__ float tf32r(float x) {
    uint32_t r;
    asm("cvt.rna.tf32.f32 %0, %1;" : "=r"(r) : "f"(x));
    return __uint_as_float(r);
}

__device__ __forceinline__ float fast_ex2(float f) {
    float e;
    asm("ex2.approx.f32 %0, %1;" : "=f"(e) : "f"(f));
    return e;
}

#define MMA_TF32(d0, d1, d2, d3, a0, a1, a2, a3, b0, b1)                    \
    asm volatile(                                                           \
        "mma.sync.aligned.m16n8k8.row.col.f32.tf32.tf32.f32 "               \
        "{%0,%1,%2,%3}, {%4,%5,%6,%7}, {%8,%9}, {%0,%1,%2,%3};"             \
        : "+f"(d0), "+f"(d1), "+f"(d2), "+f"(d3)                            \
        : "r"(a0), "r"(a1), "r"(a2), "r"(a3), "r"(b0), "r"(b1))

// Kahan compensated add (no muls -> safe under fma contraction)
__device__ __forceinline__ void kadd(float& s, float& comp, float v) {
    float y = v - comp;
    float t = s + y;
    comp = (t - s) - y;
    s = t;
}

// scatter a gmem float4 of the Q tile into fragment-major (hi,lo) smem
__device__ __forceinline__ void storeA(float* Ah, float* Al, int idx, float4 v) {
    int row = idx >> 4, c4 = (idx & 15) * 4;
    int ks = c4 >> 3, half = (c4 >> 2) & 1;
    int fb = ((row >> 4) * 8 + ks) * 32;
    int slot = ((row >> 3) & 1) + 2 * half;
    int lanebase = (row & 7) * 4;
    float hv[4], lv[4];
    hv[0] = tf32r(v.x); lv[0] = tf32r(v.x - hv[0]);
    hv[1] = tf32r(v.y); lv[1] = tf32r(v.y - hv[1]);
    hv[2] = tf32r(v.z); lv[2] = tf32r(v.z - hv[2]);
    hv[3] = tf32r(v.w); lv[3] = tf32r(v.w - hv[3]);
#pragma unroll
    for (int j = 0; j < 4; ++j) {
        int p = (fb + ((lanebase + j) ^ ks)) * 4 + slot;
        Ah[p] = hv[j];
        Al[p] = lv[j];
    }
}

// scatter a gmem float4 of the K tile into fragment-major (hi,lo) smem
__device__ __forceinline__ void storeB(float* Bh, float* Bl, int idx, float4 v) {
    int key = idx >> 4, c4 = (idx & 15) * 4;
    int ks = c4 >> 3, slot = (c4 >> 2) & 1;
    int fb = ((key >> 3) * 8 + ks) * 32;
    int lanebase = (key & 7) * 4;
    float hv[4], lv[4];
    hv[0] = tf32r(v.x); lv[0] = tf32r(v.x - hv[0]);
    hv[1] = tf32r(v.y); lv[1] = tf32r(v.y - hv[1]);
    hv[2] = tf32r(v.z); lv[2] = tf32r(v.z - hv[2]);
    hv[3] = tf32r(v.w); lv[3] = tf32r(v.w - hv[3]);
#pragma unroll
    for (int j = 0; j < 4; ++j) {
        int p = (fb + ((lanebase + j) ^ ks)) * 2 + slot;
        Bh[p] = hv[j];
        Bl[p] = lv[j];
    }
}

// ---------------------------------------------------------------------------
// Pass 1: per-query streaming KL via tf32x3 mma.sync, fragment-major smem.
// CTA = 512 thr (16 warps, 4x4 grid), 128 q x 2048 k, 16 K-tiles of 128.
// ---------------------------------------------------------------------------
__global__ void __launch_bounds__(512, 1) kl_mma(const float* __restrict__ Q,
                                                 const float* __restrict__ Km) {
    extern __shared__ float sm[];
    float* Ah = sm + OFF_AHI;
    float* Al = sm + OFF_ALO;
    float* Bh = sm + OFF_BHI;
    float* Bl = sm + OFF_BLO;
    float* red = sm + OFF_RED;

    const int tid = threadIdx.x;
    const int lane = tid & 31, wid = tid >> 5;
    const int wm = wid >> 2, wn = wid & 3;   // warp grid 4 x 4
    const int g = lane >> 2, c = lane & 3;   // fragment lane coords
    const int bh = blockIdx.x, b = bh >> 4, h = bh & 15;
    const int q0 = blockIdx.y * TQ;

    const float* Qb = Q + ((size_t)b * L + q0) * DM + h * DH;
    const float* Kb = Km + (size_t)b * L * DM + h * DH;

    // load + split Q tile [128 x 64]
#pragma unroll
    for (int it = 0; it < 4; ++it) {
        int idx = it * 512 + tid;
        int row = idx >> 4, c4 = (idx & 15) * 4;
        float4 v = *reinterpret_cast<const float4*>(Qb + (size_t)row * DM + c4);
        storeA(Ah, Al, idx, v);
    }
    // load + split K tile 0
#pragma unroll
    for (int it = 0; it < 4; ++it) {
        int idx = it * 512 + tid;
        int row = idx >> 4, c4 = (idx & 15) * 4;
        float4 v = *reinterpret_cast<const float4*>(Kb + (size_t)row * DM + c4);
        storeB(Bh, Bl, idx, v);
    }
    __syncthreads();

    float te[4], tse[4], tec[4], tsec[4];
#pragma unroll
    for (int i = 0; i < 4; ++i) { te[i] = tse[i] = tec[i] = tsec[i] = 0.f; }

    for (int t = 0; t < NT; ++t) {
        // prefetch next K tile into registers (latency hides behind mma phase)
        float4 pf[4];
        if (t + 1 < NT) {
            const float* Kt = Kb + (size_t)(t + 1) * TK * DM;
#pragma unroll
            for (int it = 0; it < 4; ++it) {
                int idx = it * 512 + tid;
                int row = idx >> 4, c4 = (idx & 15) * 4;
                pf[it] = *reinterpret_cast<const float4*>(Kt + (size_t)row * DM + c4);
            }
        }

        float acc[2][4][4];
#pragma unroll
        for (int mt = 0; mt < 2; ++mt)
#pragma unroll
            for (int nt = 0; nt < 4; ++nt)
#pragma unroll
                for (int r = 0; r < 4; ++r) acc[mt][nt][r] = 0.f;

        // --- 3-split tf32 MMA over this K tile (vectorized fragment loads) ---
#pragma unroll
        for (int sp = 0; sp < 3; ++sp) {
            const float* As = (sp == 2) ? Al : Ah;
            const float* Bs = (sp == 1) ? Bl : Bh;
#pragma unroll
            for (int ks = 0; ks < 8; ++ks) {
                const int lx = lane ^ ks;
                uint32_t a[2][4];
#pragma unroll
                for (int mt = 0; mt < 2; ++mt) {
                    float4 av = *reinterpret_cast<const float4*>(
                        As + (size_t)(((wm * 2 + mt) * 8 + ks) * 32 + lx) * 4);
                    a[mt][0] = __float_as_uint(av.x);
                    a[mt][1] = __float_as_uint(av.y);
                    a[mt][2] = __float_as_uint(av.z);
                    a[mt][3] = __float_as_uint(av.w);
                }
#pragma unroll
                for (int nt = 0; nt < 4; ++nt) {
                    float2 bv = *reinterpret_cast<const float2*>(
                        Bs + (size_t)(((wn * 4 + nt) * 8 + ks) * 32 + lx) * 2);
                    uint32_t b0 = __float_as_uint(bv.x);
                    uint32_t b1 = __float_as_uint(bv.y);
#pragma unroll
                    for (int mt = 0; mt < 2; ++mt)
                        MMA_TF32(acc[mt][nt][0], acc[mt][nt][1],
                                 acc[mt][nt][2], acc[mt][nt][3],
                                 a[mt][0], a[mt][1], a[mt][2], a[mt][3], b0, b1);
                }
            }
        }

        // --- epilogue: ex2-based exp + fp32 tile partials -> Kahan merge ---
        float tte[4], ttse[4];
#pragma unroll
        for (int i = 0; i < 4; ++i) { tte[i] = ttse[i] = 0.f; }
#pragma unroll
        for (int mt = 0; mt < 2; ++mt)
#pragma unroll
            for (int nt = 0; nt < 4; ++nt)
#pragma unroll
                for (int r = 0; r < 4; ++r) {
                    float sraw = acc[mt][nt][r];
                    float s = sraw * SCALE;
                    float e = fast_ex2(sraw * (SCALE * LOG2E));
                    int slot = mt * 2 + (r >> 1);
                    tte[slot] += e;
                    ttse[slot] = fmaf(s, e, ttse[slot]);
                }
#pragma unroll
        for (int i = 0; i < 4; ++i) {
            kadd(te[i], tec[i], tte[i]);
            kadd(tse[i], tsec[i], ttse[i]);
        }

        __syncthreads();
        if (t + 1 < NT) {
#pragma unroll
            for (int it = 0; it < 4; ++it) {
                int idx = it * 512 + tid;
                storeB(Bh, Bl, idx, pf[it]);
            }
            __syncthreads();
        }
    }

    // fold compensation, reduce across the 4 lanes of each quad (c = 0..3)
#pragma unroll
    for (int i = 0; i < 4; ++i) {
        float s1 = te[i] + tec[i];
        float s2 = tse[i] + tsec[i];
        s1 += __shfl_xor_sync(0xFFFFFFFFu, s1, 1);
        s1 += __shfl_xor_sync(0xFFFFFFFFu, s1, 2);
        s2 += __shfl_xor_sync(0xFFFFFFFFu, s2, 1);
        s2 += __shfl_xor_sync(0xFFFFFFFFu, s2, 2);
        te[i] = s1;
        tse[i] = s2;
    }
    if (c == 0) {
#pragma unroll
        for (int slot = 0; slot < 4; ++slot) {
            int row = wm * 32 + (slot >> 1) * 16 + g + (slot & 1) * 8;
            red[row * 8 + wn * 2 + 0] = te[slot];
            red[row * 8 + wn * 2 + 1] = tse[slot];
        }
    }
    __syncthreads();

    if (tid < TQ) {
        int row = tid;
        float se = red[row * 8 + 0] + red[row * 8 + 2] +
                   red[row * 8 + 4] + red[row * 8 + 6];
        float ss = red[row * 8 + 1] + red[row * 8 + 3] +
                   red[row * 8 + 5] + red[row * 8 + 7];
        const int gi = bh * L + q0 + row;
        g_sume[gi] = se;
        g_kl[gi] = (float)((double)ss / (double)se - log((double)se) + LOGL);
    }
}

// ---------------------------------------------------------------------------
// Pass 2: iterative top-U argmax per (b,h). Ties -> lowest index (JAX top_k).
// ---------------------------------------------------------------------------
__global__ void __launch_bounds__(256) topk_pass() {
    const int bh  = blockIdx.x;
    const int tid = threadIdx.x;

    __shared__ float sv[L];
    __shared__ float rv[256];
    __shared__ int   ri[256];

    for (int i = tid; i < L; i += 256) sv[i] = g_kl[bh * L + i];
    __syncthreads();

    for (int u = 0; u < U; ++u) {
        float best = -INFINITY;
        int   bi   = L;
        for (int i = tid; i < L; i += 256) {
            float v = sv[i];
            if (v > best) { best = v; bi = i; }
        }
        rv[tid] = best;
        ri[tid] = bi;
        __syncthreads();
        for (int s = 128; s > 0; s >>= 1) {
            if (tid < s) {
                float v2 = rv[tid + s];
                int   i2 = ri[tid + s];
                if (v2 > rv[tid] || (v2 == rv[tid] && i2 < ri[tid])) {
                    rv[tid] = v2; ri[tid] = i2;
                }
            }
            __syncthreads();
        }
        if (tid == 0) {
            g_idx[bh * U + u] = ri[0];
            sv[ri[0]] = -INFINITY;
        }
        __syncthreads();
    }
}

// ---------------------------------------------------------------------------
// Pass 3: sparse attention for the U selected queries of each (b,h).
// Reuses pass-1 softmax denominators (sum of exp over full K, unshifted).
// ---------------------------------------------------------------------------
constexpr int KT3 = 64;

__global__ void __launch_bounds__(256) sparse_attn(const float* __restrict__ Q,
                                                   const float* __restrict__ Km,
                                                   const float* __restrict__ Vm,
                                                   float* __restrict__ out,
                                                   float* __restrict__ aw,
                                                   int write_aw) {
    const int bh  = blockIdx.x;
    const int b   = bh >> 4;
    const int h   = bh & 15;
    const int tid = threadIdx.x;

    __shared__ float qs[U][DH];
    __shared__ float se[U];
    __shared__ int   qidx[U];
    __shared__ float tile[KT3][DH + 1];
    __shared__ float w[U][KT3];

    if (tid < U) {
        int qi = g_idx[bh * U + tid];
        qidx[tid] = qi;
        se[tid]   = g_sume[bh * L + qi];
    }
    __syncthreads();
    for (int i = tid; i < U * DH; i += 256) {
        int u = i / DH, d = i % DH;
        qs[u][d] = Q[((size_t)b * L + qidx[u]) * DM + h * DH + d];
    }

    float acc[10];
#pragma unroll
    for (int j = 0; j < 10; ++j) acc[j] = 0.f;

    const float* Kb = Km + (size_t)b * L * DM + h * DH;
    const float* Vb = Vm + (size_t)b * L * DM + h * DH;

    for (int k0 = 0; k0 < L; k0 += KT3) {
        __syncthreads();
        for (int i = tid; i < KT3 * 16; i += 256) {
            int kk = i >> 4, d4 = i & 15;
            float4 v = reinterpret_cast<const float4*>(Kb + (size_t)(k0 + kk) * DM)[d4];
            tile[kk][d4 * 4 + 0] = v.x; tile[kk][d4 * 4 + 1] = v.y;
            tile[kk][d4 * 4 + 2] = v.z; tile[kk][d4 * 4 + 3] = v.w;
        }
        __syncthreads();
        for (int i = tid; i < U * KT3; i += 256) {
            int u = i / KT3, kk = i % KT3;
            float s = 0.f;
#pragma unroll
            for (int d = 0; d < DH; ++d) s = fmaf(qs[u][d], tile[kk][d], s);
            s *= SCALE;
            float ww = fast_ex2(s * LOG2E) / se[u];
            w[u][kk] = ww;
            if (write_aw) aw[((size_t)bh * U + u) * L + k0 + kk] = ww;
        }
        __syncthreads();
        for (int i = tid; i < KT3 * 16; i += 256) {
            int kk = i >> 4, d4 = i & 15;
            float4 v = reinterpret_cast<const float4*>(Vb + (size_t)(k0 + kk) * DM)[d4];
            tile[kk][d4 * 4 + 0] = v.x; tile[kk][d4 * 4 + 1] = v.y;
            tile[kk][d4 * 4 + 2] = v.z; tile[kk][d4 * 4 + 3] = v.w;
        }
        __syncthreads();
#pragma unroll
        for (int j = 0; j < 10; ++j) {
            int item = tid + j * 256;
            if (item < U * DH) {
                int u = item / DH, d = item % DH;
                float a = acc[j];
#pragma unroll
                for (int kk = 0; kk < KT3; ++kk) a = fmaf(w[u][kk], tile[kk][d], a);
                acc[j] = a;
            }
        }
    }
    __syncthreads();

#pragma unroll
    for (int j = 0; j < 10; ++j) {
        int item = tid + j * 256;
        if (item < U * DH) {
            int u = item / DH, d = item % DH;
            out[((size_t)b * L + qidx[u]) * DM + h * DH + d] = acc[j];
        }
    }
}

// ---------------------------------------------------------------------------
extern "C" void kernel_launch(void* const* d_in, const int* in_sizes, int n_in,
                              void* d_out, int out_size) {
    const float* Q = (const float*)d_in[0];
    const float* K = (const float*)d_in[1];
    const float* V = (const float*)d_in[2];
    float* out = (float*)d_out;

    const size_t out_elems = (size_t)B * L * DM;
    const size_t aw_elems  = (size_t)BH * U * L;
    const int write_aw = ((size_t)out_size >= out_elems + aw_elems) ? 1 : 0;
    float* aw = out + out_elems;

    cudaFuncSetAttribute(kl_mma, cudaFuncAttributeMaxDynamicSharedMemorySize,
                         SMEM_BYTES);

    cudaMemsetAsync(d_out, 0, out_elems * sizeof(float), 0);

    kl_mma<<<dim3(BH, L / TQ), 512, SMEM_BYTES>>>(Q, K);
    topk_pass<<<BH, 256>>>();
    sparse_attn<<<BH, 256>>>(Q, K, V, out, aw, write_aw);
}

// round 17
// speedup vs baseline: 2.4878x; 1.6756x over previous
#include <cuda_runtime.h>
#include <math.h>
#include <stdint.h>

namespace {
constexpr int B  = 4;
constexpr int L  = 2048;
constexpr int DM = 1024;
constexpr int H  = 16;
constexpr int DH = 64;
constexpr int U  = 38;          // int(5 * ln(2048))
constexpr int BH = B * H;       // 64
constexpr float SCALE = 0.125f; // 1/sqrt(64)
constexpr float LOG2E = 1.4426950408889634f;
constexpr double LOGL = 7.624618986159398; // ln(2048)

constexpr int TQ = 128;    // queries per CTA
constexpr int TK = 128;    // keys per tile
constexpr int NT = L / TK; // 16 tiles

// fragment-major fp32/tf32 smem (float units):
//  Ah/Al: [rowblk(8)][ks(8)][lane(32)] float4 = 8192 floats (32 KB) each
//  Bh/Bl: [keyblk(16)][ks(8)][lane(32)] float2 = 8192 floats (32 KB) each, x2 bufs
constexpr int OFF_AH  = 0;
constexpr int OFF_AL  = 8192;
constexpr int OFF_BH0 = 16384;
constexpr int OFF_BL0 = 24576;
constexpr int OFF_BH1 = 32768;
constexpr int OFF_BL1 = 40960;
constexpr int OFF_RED = 49152;             // red[128][8] floats
constexpr int SMEM_BYTES = (49152 + 1024) * 4;   // 200,704 B

__device__ float g_kl[BH * L];
__device__ float g_sume[BH * L];
__device__ int   g_idx[BH * U];
} // namespace

// round-to-nearest tf32 (bit pattern in fp32 container, low 13 bits zero)
__device__ __forceinline__ float tf32r(float x) {
    uint32_t r;
    asm("cvt.rna.tf32.f32 %0, %1;" : "=r"(r) : "f"(x));
    return __uint_as_float(r);
}

__device__ __forceinline__ float fast_ex2(float f) {
    float e;
    asm("ex2.approx.f32 %0, %1;" : "=f"(e) : "f"(f));
    return e;
}

#define MMA_TF32(d0, d1, d2, d3, a0, a1, a2, a3, b0, b1)                    \
    asm volatile(                                                           \
        "mma.sync.aligned.m16n8k8.row.col.f32.tf32.tf32.f32 "               \
        "{%0,%1,%2,%3}, {%4,%5,%6,%7}, {%8,%9}, {%0,%1,%2,%3};"             \
        : "+f"(d0), "+f"(d1), "+f"(d2), "+f"(d3)                            \
        : "r"(a0), "r"(a1), "r"(a2), "r"(a3), "r"(b0), "r"(b1))

// Kahan compensated add (no muls -> safe under fma contraction)
__device__ __forceinline__ void kadd(float& s, float& comp, float v) {
    float y = v - comp;
    float t = s + y;
    comp = (t - s) - y;
    s = t;
}

// ---- tf32 hi/lo split + fragment-major scatter ---------------------------
// idx enumerates float4s of a [128 x 64] tile: row = idx>>4, c4 = (idx&15)*4.

__device__ __forceinline__ void storeA(float* Ah, float* Al, int idx, float4 v) {
    int row = idx >> 4, c4 = (idx & 15) * 4;
    int ks = c4 >> 3, half = (c4 >> 2) & 1;
    int fb = ((row >> 4) * 8 + ks) * 32;
    int slot = half * 2 + ((row >> 3) & 1);   // a0..a3 position
    int lanebase = (row & 7) * 4;
    float hv[4], lv[4];
    hv[0] = tf32r(v.x); lv[0] = tf32r(v.x - hv[0]);
    hv[1] = tf32r(v.y); lv[1] = tf32r(v.y - hv[1]);
    hv[2] = tf32r(v.z); lv[2] = tf32r(v.z - hv[2]);
    hv[3] = tf32r(v.w); lv[3] = tf32r(v.w - hv[3]);
#pragma unroll
    for (int j = 0; j < 4; ++j) {
        int p = (fb + ((lanebase + j) ^ ks)) * 4 + slot;
        Ah[p] = hv[j];
        Al[p] = lv[j];
    }
}

__device__ __forceinline__ void storeB(float* Bh, float* Bl, int idx, float4 v) {
    int key = idx >> 4, c4 = (idx & 15) * 4;
    int ks = c4 >> 3, half = (c4 >> 2) & 1;   // half selects b0/b1
    int fb = ((key >> 3) * 8 + ks) * 32;
    int lanebase = (key & 7) * 4;
    float hv[4], lv[4];
    hv[0] = tf32r(v.x); lv[0] = tf32r(v.x - hv[0]);
    hv[1] = tf32r(v.y); lv[1] = tf32r(v.y - hv[1]);
    hv[2] = tf32r(v.z); lv[2] = tf32r(v.z - hv[2]);
    hv[3] = tf32r(v.w); lv[3] = tf32r(v.w - hv[3]);
#pragma unroll
    for (int j = 0; j < 4; ++j) {
        int p = (fb + ((lanebase + j) ^ ks)) * 2 + half;
        Bh[p] = hv[j];
        Bl[p] = lv[j];
    }
}

// ---------------------------------------------------------------------------
// Pass 1: per-query streaming KL via tf32x3 mma.sync (hi.hi + hi.lo + lo.hi).
// Fragment-major smem, all 4 fragment sets loaded ONCE per k-step.
// CTA = 512 thr (16 warps, 4x4 grid), 128 q x 2048 k, B double-buffered.
// ---------------------------------------------------------------------------
__global__ void __launch_bounds__(512, 1) kl_mma(const float* __restrict__ Q,
                                                 const float* __restrict__ Km) {
    extern __shared__ float smf[];
    float* red = smf + OFF_RED;

    const int tid = threadIdx.x;
    const int lane = tid & 31, wid = tid >> 5;
    const int wm = wid >> 2, wn = wid & 3;   // warp grid 4 x 4
    const int g = lane >> 2, c = lane & 3;   // fragment lane coords
    const int bh = blockIdx.x, b = bh >> 4, h = bh & 15;
    const int q0 = blockIdx.y * TQ;

    const float* Qb = Q + ((size_t)b * L + q0) * DM + h * DH;
    const float* Kb = Km + (size_t)b * L * DM + h * DH;

    // load + split Q tile [128 x 64]
#pragma unroll
    for (int it = 0; it < 4; ++it) {
        int idx = it * 512 + tid;
        int row = idx >> 4, c4 = (idx & 15) * 4;
        float4 v = *reinterpret_cast<const float4*>(Qb + (size_t)row * DM + c4);
        storeA(smf + OFF_AH, smf + OFF_AL, idx, v);
    }
    // load + split K tile 0 into buffer 0
#pragma unroll
    for (int it = 0; it < 4; ++it) {
        int idx = it * 512 + tid;
        int row = idx >> 4, c4 = (idx & 15) * 4;
        float4 v = *reinterpret_cast<const float4*>(Kb + (size_t)row * DM + c4);
        storeB(smf + OFF_BH0, smf + OFF_BL0, idx, v);
    }
    __syncthreads();

    const uint4* Ah4 = reinterpret_cast<const uint4*>(smf + OFF_AH);
    const uint4* Al4 = reinterpret_cast<const uint4*>(smf + OFF_AL);

    float te[4], tse[4], tec[4], tsec[4];
#pragma unroll
    for (int i = 0; i < 4; ++i) { te[i] = tse[i] = tec[i] = tsec[i] = 0.f; }

    for (int t = 0; t < NT; ++t) {
        const uint2* Bh2 = reinterpret_cast<const uint2*>(
            smf + ((t & 1) ? OFF_BH1 : OFF_BH0));
        const uint2* Bl2 = reinterpret_cast<const uint2*>(
            smf + ((t & 1) ? OFF_BL1 : OFF_BL0));

        // prefetch next K tile into registers (hidden behind MMA phase)
        float4 pf[4];
        if (t + 1 < NT) {
            const float* Kt = Kb + (size_t)(t + 1) * TK * DM;
#pragma unroll
            for (int it = 0; it < 4; ++it) {
                int idx = it * 512 + tid;
                int row = idx >> 4, c4 = (idx & 15) * 4;
                pf[it] = *reinterpret_cast<const float4*>(Kt + (size_t)row * DM + c4);
            }
        }

        float acc[2][4][4];
#pragma unroll
        for (int mt = 0; mt < 2; ++mt)
#pragma unroll
            for (int nt = 0; nt < 4; ++nt)
#pragma unroll
                for (int r = 0; r < 4; ++r) acc[mt][nt][r] = 0.f;

        // --- per k-step: load 4 fragment sets once, issue 3 products ---
#pragma unroll
        for (int ks = 0; ks < 8; ++ks) {
            const int lx = lane ^ ks;
            uint4 ah[2], al[2];
#pragma unroll
            for (int mt = 0; mt < 2; ++mt) {
                ah[mt] = Ah4[((wm * 2 + mt) * 8 + ks) * 32 + lx];
                al[mt] = Al4[((wm * 2 + mt) * 8 + ks) * 32 + lx];
            }
            uint2 bh[4], bl[4];
#pragma unroll
            for (int nt = 0; nt < 4; ++nt) {
                bh[nt] = Bh2[((wn * 4 + nt) * 8 + ks) * 32 + lx];
                bl[nt] = Bl2[((wn * 4 + nt) * 8 + ks) * 32 + lx];
            }
            // hi . hi
#pragma unroll
            for (int nt = 0; nt < 4; ++nt)
#pragma unroll
                for (int mt = 0; mt < 2; ++mt)
                    MMA_TF32(acc[mt][nt][0], acc[mt][nt][1],
                             acc[mt][nt][2], acc[mt][nt][3],
                             ah[mt].x, ah[mt].y, ah[mt].z, ah[mt].w,
                             bh[nt].x, bh[nt].y);
            // hi . lo
#pragma unroll
            for (int nt = 0; nt < 4; ++nt)
#pragma unroll
                for (int mt = 0; mt < 2; ++mt)
                    MMA_TF32(acc[mt][nt][0], acc[mt][nt][1],
                             acc[mt][nt][2], acc[mt][nt][3],
                             ah[mt].x, ah[mt].y, ah[mt].z, ah[mt].w,
                             bl[nt].x, bl[nt].y);
            // lo . hi
#pragma unroll
            for (int nt = 0; nt < 4; ++nt)
#pragma unroll
                for (int mt = 0; mt < 2; ++mt)
                    MMA_TF32(acc[mt][nt][0], acc[mt][nt][1],
                             acc[mt][nt][2], acc[mt][nt][3],
                             al[mt].x, al[mt].y, al[mt].z, al[mt].w,
                             bh[nt].x, bh[nt].y);
        }

        // store prefetched tile into the other buffer (overlaps epilogue)
        if (t + 1 < NT) {
            float* BhN = smf + (((t + 1) & 1) ? OFF_BH1 : OFF_BH0);
            float* BlN = smf + (((t + 1) & 1) ? OFF_BL1 : OFF_BL0);
#pragma unroll
            for (int it = 0; it < 4; ++it)
                storeB(BhN, BlN, it * 512 + tid, pf[it]);
        }

        // --- epilogue: ex2-based exp + fp32 tile partials -> Kahan merge ---
        float tte[4], ttse[4];
#pragma unroll
        for (int i = 0; i < 4; ++i) { tte[i] = ttse[i] = 0.f; }
#pragma unroll
        for (int mt = 0; mt < 2; ++mt)
#pragma unroll
            for (int nt = 0; nt < 4; ++nt)
#pragma unroll
                for (int r = 0; r < 4; ++r) {
                    float sraw = acc[mt][nt][r];
                    float s = sraw * SCALE;
                    float e = fast_ex2(sraw * (SCALE * LOG2E));
                    int slot = mt * 2 + (r >> 1);
                    tte[slot] += e;
                    ttse[slot] = fmaf(s, e, ttse[slot]);
                }
#pragma unroll
        for (int i = 0; i < 4; ++i) {
            kadd(te[i], tec[i], tte[i]);
            kadd(tse[i], tsec[i], ttse[i]);
        }

        __syncthreads();
    }

    // fold compensation, reduce across the 4 lanes of each quad (c = 0..3)
#pragma unroll
    for (int i = 0; i < 4; ++i) {
        float s1 = te[i] + tec[i];
        float s2 = tse[i] + tsec[i];
        s1 += __shfl_xor_sync(0xFFFFFFFFu, s1, 1);
        s1 += __shfl_xor_sync(0xFFFFFFFFu, s1, 2);
        s2 += __shfl_xor_sync(0xFFFFFFFFu, s2, 1);
        s2 += __shfl_xor_sync(0xFFFFFFFFu, s2, 2);
        te[i] = s1;
        tse[i] = s2;
    }
    if (c == 0) {
#pragma unroll
        for (int slot = 0; slot < 4; ++slot) {
            int row = wm * 32 + (slot >> 1) * 16 + g + (slot & 1) * 8;
            red[row * 8 + wn * 2 + 0] = te[slot];
            red[row * 8 + wn * 2 + 1] = tse[slot];
        }
    }
    __syncthreads();

    if (tid < TQ) {
        int row = tid;
        float se = red[row * 8 + 0] + red[row * 8 + 2] +
                   red[row * 8 + 4] + red[row * 8 + 6];
        float ss = red[row * 8 + 1] + red[row * 8 + 3] +
                   red[row * 8 + 5] + red[row * 8 + 7];
        const int gi = bh * L + q0 + row;
        g_sume[gi] = se;
        g_kl[gi] = (float)((double)ss / (double)se - log((double)se) + LOGL);
    }
}

// ---------------------------------------------------------------------------
// Pass 2: iterative top-U argmax per (b,h). Ties -> lowest index (JAX top_k).
// ---------------------------------------------------------------------------
__global__ void __launch_bounds__(256) topk_pass() {
    const int bh  = blockIdx.x;
    const int tid = threadIdx.x;

    __shared__ float sv[L];
    __shared__ float rv[256];
    __shared__ int   ri[256];

    for (int i = tid; i < L; i += 256) sv[i] = g_kl[bh * L + i];
    __syncthreads();

    for (int u = 0; u < U; ++u) {
        float best = -INFINITY;
        int   bi   = L;
        for (int i = tid; i < L; i += 256) {
            float v = sv[i];
            if (v > best) { best = v; bi = i; }
        }
        rv[tid] = best;
        ri[tid] = bi;
        __syncthreads();
        for (int s = 128; s > 0; s >>= 1) {
            if (tid < s) {
                float v2 = rv[tid + s];
                int   i2 = ri[tid + s];
                if (v2 > rv[tid] || (v2 == rv[tid] && i2 < ri[tid])) {
                    rv[tid] = v2; ri[tid] = i2;
                }
            }
            __syncthreads();
        }
        if (tid == 0) {
            g_idx[bh * U + u] = ri[0];
            sv[ri[0]] = -INFINITY;
        }
        __syncthreads();
    }
}

// ---------------------------------------------------------------------------
// Pass 3: sparse attention, split NSPLIT ways over the key range.
// Partial outputs combined via atomicAdd (out zeroed by memset upfront).
// ---------------------------------------------------------------------------
constexpr int KT3 = 64;
constexpr int NSPLIT = 8;
constexpr int KRANGE = L / NSPLIT;   // 256 keys per split

__global__ void __launch_bounds__(256) sparse_attn(const float* __restrict__ Q,
                                                   const float* __restrict__ Km,
                                                   const float* __restrict__ Vm,
                                                   float* __restrict__ out,
                                                   float* __restrict__ aw,
                                                   int write_aw) {
    const int bh  = blockIdx.x;
    const int b   = bh >> 4;
    const int h   = bh & 15;
    const int ks0 = blockIdx.y * KRANGE;
    const int tid = threadIdx.x;

    __shared__ float qs[U][DH];
    __shared__ float se[U];
    __shared__ int   qidx[U];
    __shared__ float tile[KT3][DH + 1];
    __shared__ float w[U][KT3];

    if (tid < U) {
        int qi = g_idx[bh * U + tid];
        qidx[tid] = qi;
        se[tid]   = g_sume[bh * L + qi];
    }
    __syncthreads();
    for (int i = tid; i < U * DH; i += 256) {
        int u = i / DH, d = i % DH;
        qs[u][d] = Q[((size_t)b * L + qidx[u]) * DM + h * DH + d];
    }

    float acc[10];
#pragma unroll
    for (int j = 0; j < 10; ++j) acc[j] = 0.f;

    const float* Kb = Km + (size_t)b * L * DM + h * DH;
    const float* Vb = Vm + (size_t)b * L * DM + h * DH;

    for (int k0 = ks0; k0 < ks0 + KRANGE; k0 += KT3) {
        __syncthreads();
        for (int i = tid; i < KT3 * 16; i += 256) {
            int kk = i >> 4, d4 = i & 15;
            float4 v = reinterpret_cast<const float4*>(Kb + (size_t)(k0 + kk) * DM)[d4];
            tile[kk][d4 * 4 + 0] = v.x; tile[kk][d4 * 4 + 1] = v.y;
            tile[kk][d4 * 4 + 2] = v.z; tile[kk][d4 * 4 + 3] = v.w;
        }
        __syncthreads();
        for (int i = tid; i < U * KT3; i += 256) {
            int u = i / KT3, kk = i % KT3;
            float s = 0.f;
#pragma unroll
            for (int d = 0; d < DH; ++d) s = fmaf(qs[u][d], tile[kk][d], s);
            s *= SCALE;
            float ww = fast_ex2(s * LOG2E) / se[u];
            w[u][kk] = ww;
            if (write_aw) aw[((size_t)bh * U + u) * L + k0 + kk] = ww;
        }
        __syncthreads();
        for (int i = tid; i < KT3 * 16; i += 256) {
            int kk = i >> 4, d4 = i & 15;
            float4 v = reinterpret_cast<const float4*>(Vb + (size_t)(k0 + kk) * DM)[d4];
            tile[kk][d4 * 4 + 0] = v.x; tile[kk][d4 * 4 + 1] = v.y;
            tile[kk][d4 * 4 + 2] = v.z; tile[kk][d4 * 4 + 3] = v.w;
        }
        __syncthreads();
#pragma unroll
        for (int j = 0; j < 10; ++j) {
            int item = tid + j * 256;
            if (item < U * DH) {
                int u = item / DH, d = item % DH;
                float a = acc[j];
#pragma unroll
                for (int kk = 0; kk < KT3; ++kk) a = fmaf(w[u][kk], tile[kk][d], a);
                acc[j] = a;
            }
        }
    }
    __syncthreads();

#pragma unroll
    for (int j = 0; j < 10; ++j) {
        int item = tid + j * 256;
        if (item < U * DH) {
            int u = item / DH, d = item % DH;
            atomicAdd(&out[((size_t)b * L + qidx[u]) * DM + h * DH + d], acc[j]);
        }
    }
}

// ---------------------------------------------------------------------------
extern "C" void kernel_launch(void* const* d_in, const int* in_sizes, int n_in,
                              void* d_out, int out_size) {
    const float* Q = (const float*)d_in[0];
    const float* K = (const float*)d_in[1];
    const float* V = (const float*)d_in[2];
    float* out = (float*)d_out;

    const size_t out_elems = (size_t)B * L * DM;
    const size_t aw_elems  = (size_t)BH * U * L;
    const int write_aw = ((size_t)out_size >= out_elems + aw_elems) ? 1 : 0;
    float* aw = out + out_elems;

    cudaFuncSetAttribute(kl_mma, cudaFuncAttributeMaxDynamicSharedMemorySize,
                         SMEM_BYTES);

    cudaMemsetAsync(d_out, 0, out_elems * sizeof(float), 0);

    kl_mma<<<dim3(BH, L / TQ), 512, SMEM_BYTES>>>(Q, K);
    topk_pass<<<BH, 256>>>();
    sparse_attn<<<dim3(BH, NSPLIT), 256>>>(Q, K, V, out, aw, write_aw);
}